// round 4
// baseline (speedup 1.0000x reference)
#include <cuda_runtime.h>

#define B_   16
#define N_   4096
#define C_   256
#define NH   8
#define HD   32
#define M_   (B_ * N_)

__device__ __align__(16) float g_Q[M_ * C_];
__device__ __align__(16) float g_K[M_ * C_];
__device__ __align__(16) float g_V[M_ * C_];
__device__ __align__(16) float g_O[M_ * C_];
__device__ __align__(16) float g_kmean[B_ * C_];
__device__ __align__(16) float g_kvmat[B_ * NH * HD * HD];

__device__ __forceinline__ unsigned long long dup2(float v) {
    unsigned long long r;
    asm("mov.b64 %0, {%1, %1};" : "=l"(r) : "f"(v));
    return r;
}
__device__ __forceinline__ void ffma2(unsigned long long &c,
                                      unsigned long long a,
                                      unsigned long long b) {
    asm("fma.rn.f32x2 %0, %1, %2, %0;" : "+l"(c) : "l"(a), "l"(b));
}
union F4U { float4 f; unsigned long long u[2]; };

// C[M x 256] = A[M x 256] * B[256 x N-slice] (+bias). 128x128 tile, 256 thr.
__global__ __launch_bounds__(256, 2)
void sgemm_kernel(const float* __restrict__ A, const float* __restrict__ Bm,
                  int ldb, const float* __restrict__ bias, float* __restrict__ C)
{
    __shared__ float As[2][8][132];
    __shared__ float Bs[2][8][128];

    const int tid = threadIdx.x;
    const int m0  = blockIdx.y * 128;
    const int n0  = blockIdx.x * 128;
    const int ar  = tid >> 1, ac = (tid & 1) * 4;
    const int br  = tid >> 5, bc = (tid & 31) * 4;
    const int tx  = tid & 15, ty = tid >> 4;

    const float* Ap = A  + (m0 + ar) * C_ + ac;
    const float* Bp = Bm + br * ldb + n0 + bc;

    unsigned long long acc[8][4];
    #pragma unroll
    for (int i = 0; i < 8; i++)
        #pragma unroll
        for (int j = 0; j < 4; j++) acc[i][j] = 0ull;

    {
        float4 va = *(const float4*)(Ap);
        float4 vb = *(const float4*)(Bp);
        As[0][ac+0][ar] = va.x; As[0][ac+1][ar] = va.y;
        As[0][ac+2][ar] = va.z; As[0][ac+3][ar] = va.w;
        *(float4*)&Bs[0][br][bc] = vb;
    }
    __syncthreads();

    int buf = 0;
    const int KT = C_ / 8;
    for (int kt = 0; kt < KT; kt++) {
        float4 va, vb;
        if (kt + 1 < KT) {
            va = *(const float4*)(Ap + (kt + 1) * 8);
            vb = *(const float4*)(Bp + (kt + 1) * 8 * ldb);
        }
        #pragma unroll
        for (int kk = 0; kk < 8; kk++) {
            float4 a0 = *(const float4*)&As[buf][kk][ty * 4];
            float4 a1 = *(const float4*)&As[buf][kk][64 + ty * 4];
            F4U b0, b1;
            b0.f = *(const float4*)&Bs[buf][kk][tx * 4];
            b1.f = *(const float4*)&Bs[buf][kk][64 + tx * 4];
            float av[8] = {a0.x, a0.y, a0.z, a0.w, a1.x, a1.y, a1.z, a1.w};
            #pragma unroll
            for (int i = 0; i < 8; i++) {
                unsigned long long aa = dup2(av[i]);
                ffma2(acc[i][0], aa, b0.u[0]);
                ffma2(acc[i][1], aa, b0.u[1]);
                ffma2(acc[i][2], aa, b1.u[0]);
                ffma2(acc[i][3], aa, b1.u[1]);
            }
        }
        if (kt + 1 < KT) {
            int nb = buf ^ 1;
            As[nb][ac+0][ar] = va.x; As[nb][ac+1][ar] = va.y;
            As[nb][ac+2][ar] = va.z; As[nb][ac+3][ar] = va.w;
            *(float4*)&Bs[nb][br][bc] = vb;
            __syncthreads();
            buf = nb;
        }
    }

    float4 bv0 = make_float4(0.f,0.f,0.f,0.f), bv1 = bv0;
    if (bias) {
        bv0 = *(const float4*)&bias[n0 + tx * 4];
        bv1 = *(const float4*)&bias[n0 + 64 + tx * 4];
    }
    #pragma unroll
    for (int i = 0; i < 8; i++) {
        int row = m0 + ((i < 4) ? (ty * 4 + i) : (64 + ty * 4 + (i - 4)));
        F4U r0, r1;
        r0.u[0] = acc[i][0]; r0.u[1] = acc[i][1];
        r1.u[0] = acc[i][2]; r1.u[1] = acc[i][3];
        r0.f.x += bv0.x; r0.f.y += bv0.y; r0.f.z += bv0.z; r0.f.w += bv0.w;
        r1.f.x += bv1.x; r1.f.y += bv1.y; r1.f.z += bv1.z; r1.f.w += bv1.w;
        *(float4*)&C[row * C_ + n0 + tx * 4]      = r0.f;
        *(float4*)&C[row * C_ + n0 + 64 + tx * 4] = r1.f;
    }
}

// focus nonlinearity, in-place on g_Q and g_K (k gets +pos_enc). 1 warp/row.
__global__ void focus_kernel(const float* __restrict__ pos_enc,
                             const float* __restrict__ scale_param)
{
    const int lane = threadIdx.x & 31;
    const int warp = threadIdx.x >> 5;
    const int row  = blockIdx.x * 8 + warp;
    const int n    = row & (N_ - 1);
    float* qrow = g_Q + row * C_;
    float* krow = g_K + row * C_;
    const float* prow = pos_enc + n * C_;

    float tq3[8], tk3[8];
    float sq2 = 0.f, sq6 = 0.f, sk2 = 0.f, sk6 = 0.f;
    #pragma unroll
    for (int j = 0; j < 8; j++) {
        int c = lane + j * 32;
        float sp = scale_param[c];
        float s  = (sp > 20.f) ? sp : log1pf(expf(sp));
        float q  = fmaxf(qrow[c], 0.f);
        q = (q + 1e-6f) / s;
        float q3 = q * q * q;
        sq2 += q * q; sq6 += q3 * q3; tq3[j] = q3;
        float k = fmaxf(krow[c] + prow[c], 0.f);
        k = (k + 1e-6f) / s;
        float k3 = k * k * k;
        sk2 += k * k; sk6 += k3 * k3; tk3[j] = k3;
    }
    #pragma unroll
    for (int off = 16; off > 0; off >>= 1) {
        sq2 += __shfl_xor_sync(0xffffffffu, sq2, off);
        sq6 += __shfl_xor_sync(0xffffffffu, sq6, off);
        sk2 += __shfl_xor_sync(0xffffffffu, sk2, off);
        sk6 += __shfl_xor_sync(0xffffffffu, sk6, off);
    }
    float qf = sqrtf(sq2 / sq6);
    float kf = sqrtf(sk2 / sk6);
    #pragma unroll
    for (int j = 0; j < 8; j++) {
        int c = lane + j * 32;
        qrow[c] = tq3[j] * qf;
        krow[c] = tk3[j] * kf;
    }
}

__global__ void zero_kernel(float* __restrict__ p, int nElem)
{
    int i = blockIdx.x * 256 + threadIdx.x;
    if (i < nElem) p[i] = 0.f;
}

// kmean[b,c] = mean_n K[b,n,c]
__global__ void kmean_kernel()
{
    const int c = threadIdx.x;
    const int b = blockIdx.y;
    const int chunk = blockIdx.x;
    const float* p = g_K + (b * N_ + chunk * 128) * C_ + c;
    float s = 0.f;
    #pragma unroll 8
    for (int i = 0; i < 128; i++) s += p[i * C_];
    atomicAdd(&g_kmean[b * C_ + c], s * (1.f / (float)N_));
}

// kvmat[b,h,d,e] = sum_n K[b,n,h,d]*V[b,n,h,e] / N
__global__ void kvmat_kernel()
{
    const int bh = blockIdx.y;
    const int b  = bh >> 3, h = bh & 7;
    const int ns = blockIdx.x;
    const int t  = threadIdx.x;
    const int d  = t & 31, eg = t >> 5;
    __shared__ float ks[16][32], vs[16][32];
    float a0 = 0.f, a1 = 0.f, a2 = 0.f, a3 = 0.f;
    const int base = (b * N_ + ns * 512) * C_ + h * HD;

    for (int cc = 0; cc < 32; cc++) {
        const int off = base + cc * 16 * C_;
        {
            int nn = t >> 5, c = t & 31;
            ks[nn][c] = g_K[off + nn * C_ + c];
            vs[nn][c] = g_V[off + nn * C_ + c];
            int i2 = t + 256; nn = i2 >> 5; c = i2 & 31;
            ks[nn][c] = g_K[off + nn * C_ + c];
            vs[nn][c] = g_V[off + nn * C_ + c];
        }
        __syncthreads();
        #pragma unroll
        for (int nn = 0; nn < 16; nn++) {
            float  kd = ks[nn][d];
            float4 v4 = *(const float4*)&vs[nn][eg * 4];
            a0 += kd * v4.x; a1 += kd * v4.y; a2 += kd * v4.z; a3 += kd * v4.w;
        }
        __syncthreads();
    }
    const float sc = 1.f / (float)N_;
    const int  o  = (bh * HD + d) * HD + eg * 4;
    atomicAdd(&g_kvmat[o + 0], a0 * sc);
    atomicAdd(&g_kvmat[o + 1], a1 * sc);
    atomicAdd(&g_kvmat[o + 2], a2 * sc);
    atomicAdd(&g_kvmat[o + 3], a3 * sc);
}

// O[b,n,h*32+e] = (q_h . kvmat_h)_e * z,  z = 1/(q_h . kmean_h + eps)
__global__ __launch_bounds__(256, 1)
void attn_kernel()
{
    extern __shared__ float sm[];
    float* q_s = sm;                       // 256 x 33 (transposed q tile)
    float* kvs = q_s + 256 * 33;           // 8*32*32
    float* km  = kvs + NH * HD * HD;       // 256
    float* o_s = km + 256;                 // 32 x 257

    const int b    = blockIdx.y;
    const int tile = blockIdx.x;
    const int row0 = b * N_ + tile * 32;
    const int t    = threadIdx.x;

    #pragma unroll
    for (int j = 0; j < 32; j++)
        q_s[t * 33 + j] = g_Q[(row0 + j) * C_ + t];
    for (int j = t; j < NH * HD * HD; j += 256)
        kvs[j] = g_kvmat[b * NH * HD * HD + j];
    km[t] = g_kmean[b * C_ + t];
    __syncthreads();

    const int n = t & 31, h = t >> 5;
    float qv[32];
    float z = 0.f;
    #pragma unroll
    for (int d = 0; d < 32; d++) {
        qv[d] = q_s[(h * HD + d) * 33 + n];
        z += qv[d] * km[h * HD + d];
    }
    float acc[32];
    #pragma unroll
    for (int e = 0; e < 32; e++) acc[e] = 0.f;
    const float* kvh = kvs + h * HD * HD;
    #pragma unroll 4
    for (int d = 0; d < 32; d++) {
        float qd = qv[d];
        #pragma unroll
        for (int e4 = 0; e4 < 8; e4++) {
            float4 kv = *(const float4*)&kvh[d * HD + e4 * 4];
            acc[e4*4+0] += qd * kv.x;
            acc[e4*4+1] += qd * kv.y;
            acc[e4*4+2] += qd * kv.z;
            acc[e4*4+3] += qd * kv.w;
        }
    }
    float zi = 1.f / (z + 1e-6f);
    #pragma unroll
    for (int e = 0; e < 32; e++)
        o_s[n * 257 + h * HD + e] = acc[e] * zi;
    __syncthreads();
    #pragma unroll
    for (int j = 0; j < 32; j++)
        g_O[(row0 + j) * C_ + t] = o_s[j * 257 + t];
}

// depthwise 5x5 SAME conv over V viewed as (B*h, d, 64, 64), added into O
__global__ void dwconv_kernel(const float* __restrict__ Wc,
                              const float* __restrict__ bc)
{
    const int c  = threadIdx.x;
    const int y  = blockIdx.x;
    const int b  = blockIdx.y;
    const int ch = c & (HD - 1);
    float w[25];
    #pragma unroll
    for (int i = 0; i < 25; i++) w[i] = Wc[ch * 25 + i];
    const float bias = bc[ch];

    const float* vb = g_V + (b * N_) * C_ + c;
    float*       ob = g_O + (b * N_) * C_ + c;

    float win[5][5];
    #pragma unroll
    for (int wy = 0; wy < 5; wy++) {
        int Y = y + wy - 2;
        bool yin = (Y >= 0) && (Y < 64);
        #pragma unroll
        for (int wx = 0; wx < 5; wx++) {
            int X = wx - 2;
            win[wy][wx] = (yin && X >= 0) ? vb[(Y * 64 + X) * C_] : 0.f;
        }
    }
    for (int x = 0; x < 64; x++) {
        float acc = bias;
        #pragma unroll
        for (int wy = 0; wy < 5; wy++)
            #pragma unroll
            for (int wx = 0; wx < 5; wx++)
                acc += win[wy][wx] * w[wy * 5 + wx];
        ob[(y * 64 + x) * C_] += acc;
        #pragma unroll
        for (int wy = 0; wy < 5; wy++)
            #pragma unroll
            for (int wx = 0; wx < 4; wx++) win[wy][wx] = win[wy][wx + 1];
        int X = x + 3;
        bool xin = X < 64;
        #pragma unroll
        for (int wy = 0; wy < 5; wy++) {
            int Y = y + wy - 2;
            win[wy][4] = (xin && Y >= 0 && Y < 64) ? vb[(Y * 64 + X) * C_] : 0.f;
        }
    }
}

extern "C" void kernel_launch(void* const* d_in, const int* in_sizes, int n_in,
                              void* d_out, int out_size)
{
    const float* x     = (const float*)d_in[0];
    const float* Wq    = (const float*)d_in[1];
    const float* Wkv   = (const float*)d_in[2];
    const float* Wp    = (const float*)d_in[3];
    const float* bp    = (const float*)d_in[4];
    const float* scale = (const float*)d_in[5];
    const float* pos   = (const float*)d_in[6];
    const float* dwcw  = (const float*)d_in[7];
    const float* dwcb  = (const float*)d_in[8];
    float* out = (float*)d_out;

    float *Qp, *Kp, *Vp, *Op, *kmp, *kvp;
    cudaGetSymbolAddress((void**)&Qp,  g_Q);
    cudaGetSymbolAddress((void**)&Kp,  g_K);
    cudaGetSymbolAddress((void**)&Vp,  g_V);
    cudaGetSymbolAddress((void**)&Op,  g_O);
    cudaGetSymbolAddress((void**)&kmp, g_kmean);
    cudaGetSymbolAddress((void**)&kvp, g_kvmat);

    static bool attr_done = false;
    if (!attr_done) {
        const int ATTN_SMEM = (256 * 33 + NH * HD * HD + 256 + 32 * 257) * 4;
        cudaFuncSetAttribute(attn_kernel,
                             cudaFuncAttributeMaxDynamicSharedMemorySize, ATTN_SMEM);
        attr_done = true;
    }
    const int ATTN_SMEM = (256 * 33 + NH * HD * HD + 256 + 32 * 257) * 4;

    dim3 gg(2, 512);

    zero_kernel<<<(B_ * C_ + 255) / 256, 256>>>(kmp, B_ * C_);
    zero_kernel<<<(B_ * NH * HD * HD + 255) / 256, 256>>>(kvp, B_ * NH * HD * HD);

    sgemm_kernel<<<gg, 256>>>(x, Wq,        C_,      nullptr, Qp);   // q
    sgemm_kernel<<<gg, 256>>>(x, Wkv,       2 * C_,  nullptr, Kp);   // k half
    sgemm_kernel<<<gg, 256>>>(x, Wkv + C_,  2 * C_,  nullptr, Vp);   // v half

    focus_kernel<<<M_ / 8, 256>>>(pos, scale);

    kmean_kernel<<<dim3(32, B_), 256>>>();
    kvmat_kernel<<<dim3(8, B_ * NH), 256>>>();

    attn_kernel<<<dim3(N_ / 32, B_), 256, ATTN_SMEM>>>();

    dwconv_kernel<<<dim3(64, B_), 256>>>(dwcw, dwcb);

    sgemm_kernel<<<gg, 256>>>(Op, Wp, C_, bp, out);                  // out proj
}

// round 6
// speedup vs baseline: 1.2307x; 1.2307x over previous
#include <cuda_runtime.h>
#include <cuda_bf16.h>
#include <cstdint>

#define B_   16
#define N_   4096
#define C_   256
#define NH   8
#define HD   32
#define M_   (B_ * N_)

// ---------------- scratch ----------------
__device__ __align__(16) float g_Q[M_ * C_];
__device__ __align__(16) float g_K[M_ * C_];
__device__ __align__(16) float g_V[M_ * C_];
__device__ __align__(16) float g_O[M_ * C_];
__device__ __align__(16) float g_kmean[B_ * C_];
__device__ __align__(16) float g_kvmat[B_ * NH * HD * HD];
__device__ __align__(16) __nv_bfloat16 g_xhi[M_ * C_];
__device__ __align__(16) __nv_bfloat16 g_xlo[M_ * C_];
__device__ __align__(16) __nv_bfloat16 g_ohi[M_ * C_];
__device__ __align__(16) __nv_bfloat16 g_olo[M_ * C_];
__device__ __align__(16) __nv_bfloat16 g_whi[4 * C_ * C_];   // [w][n][k]
__device__ __align__(16) __nv_bfloat16 g_wlo[4 * C_ * C_];

// ---------------- helpers ----------------
__device__ __forceinline__ uint32_t smem_u32(const void* p) {
    uint32_t a;
    asm("{ .reg .u64 t; cvta.to.shared.u64 t, %1; cvt.u32.u64 %0, t; }"
        : "=r"(a) : "l"(p));
    return a;
}
#define STS128(a, r0, r1, r2, r3) \
    asm volatile("st.shared.v4.b32 [%0], {%1, %2, %3, %4};" \
                 :: "r"(a), "r"(r0), "r"(r1), "r"(r2), "r"(r3) : "memory")

#define LDSM4(d, addr) \
    asm volatile("ldmatrix.sync.aligned.m8n8.x4.shared.b16 {%0,%1,%2,%3}, [%4];" \
        : "=r"((d)[0]), "=r"((d)[1]), "=r"((d)[2]), "=r"((d)[3]) : "r"(addr))

#define MMA(c, a, b) \
    asm volatile("mma.sync.aligned.m16n8k16.row.col.f32.bf16.bf16.f32 " \
        "{%0,%1,%2,%3}, {%4,%5,%6,%7}, {%8,%9}, {%0,%1,%2,%3};" \
        : "+f"((c)[0]), "+f"((c)[1]), "+f"((c)[2]), "+f"((c)[3]) \
        : "r"((a)[0]), "r"((a)[1]), "r"((a)[2]), "r"((a)[3]), \
          "r"((b)[0]), "r"((b)[1]))

// ---------------- hi/lo conversion ----------------
union BF2U { __nv_bfloat162 b; uint32_t u; };
__device__ __forceinline__ void cvt4(float4 v, uint2& hi, uint2& lo) {
    __nv_bfloat16 h0 = __float2bfloat16_rn(v.x), h1 = __float2bfloat16_rn(v.y);
    __nv_bfloat16 h2 = __float2bfloat16_rn(v.z), h3 = __float2bfloat16_rn(v.w);
    __nv_bfloat16 l0 = __float2bfloat16_rn(v.x - __bfloat162float(h0));
    __nv_bfloat16 l1 = __float2bfloat16_rn(v.y - __bfloat162float(h1));
    __nv_bfloat16 l2 = __float2bfloat16_rn(v.z - __bfloat162float(h2));
    __nv_bfloat16 l3 = __float2bfloat16_rn(v.w - __bfloat162float(h3));
    BF2U a, b;
    a.b = __halves2bfloat162(h0, h1); b.b = __halves2bfloat162(h2, h3);
    hi = make_uint2(a.u, b.u);
    a.b = __halves2bfloat162(l0, l1); b.b = __halves2bfloat162(l2, l3);
    lo = make_uint2(a.u, b.u);
}

__global__ void cvt_hilo_kernel(const float* __restrict__ src,
                                __nv_bfloat16* __restrict__ hi,
                                __nv_bfloat16* __restrict__ lo, int n4)
{
    int i = blockIdx.x * 256 + threadIdx.x;
    if (i >= n4) return;
    float4 v = ((const float4*)src)[i];
    uint2 h, l;
    cvt4(v, h, l);
    ((uint2*)hi)[i] = h;
    ((uint2*)lo)[i] = l;
}

__global__ void prep_w_kernel(const float* __restrict__ Wq,
                              const float* __restrict__ Wkv,
                              const float* __restrict__ Wp)
{
    int k = blockIdx.x, w = blockIdx.y, n = threadIdx.x;
    float v;
    if      (w == 0) v = Wq[k * C_ + n];
    else if (w == 1) v = Wkv[k * 2 * C_ + n];
    else if (w == 2) v = Wkv[k * 2 * C_ + C_ + n];
    else             v = Wp[k * C_ + n];
    __nv_bfloat16 h = __float2bfloat16_rn(v);
    __nv_bfloat16 l = __float2bfloat16_rn(v - __bfloat162float(h));
    g_whi[(w * C_ + n) * C_ + k] = h;
    g_wlo[(w * C_ + n) * C_ + k] = l;
}

// ---------------- HMMA split-precision GEMM -----------------------------------
// C[M x 256] = (Ahi+Alo) @ (Bhi+Blo)^T (+bias).  B planes are [n][k] bf16.
// CTA 128x128, 256 thr, warp tile 64x32, K-chunks of 64, SW128-swizzled smem.
#define SM_AHI_ 0
#define SM_ALO_ 16384
#define SM_BHI_ 32768
#define SM_BLO_ 49152
#define SM_GTOT 65536

__global__ void __launch_bounds__(256, 2)
gemm_hmma(const __nv_bfloat16* __restrict__ Ahi, const __nv_bfloat16* __restrict__ Alo,
          const __nv_bfloat16* __restrict__ Bhi, const __nv_bfloat16* __restrict__ Blo,
          const float* __restrict__ bias, float* __restrict__ C)
{
    extern __shared__ char smem[];
    const uint32_t sb = smem_u32(smem);
    const int tid  = threadIdx.x;
    const int lane = tid & 31, wid = tid >> 5;
    const int wm   = wid & 1,  wn  = wid >> 1;
    const int m0   = blockIdx.y * 128;
    const int n0   = blockIdx.x * 128;

    // ldmatrix per-lane fixed address components
    const uint32_t xm   = (uint32_t)(lane & 7) << 4;
    const uint32_t aRow = wm * 64 + (lane & 15);
    const uint32_t aK   = (uint32_t)(lane >> 4) * 16;
    const uint32_t bRow = wn * 32 + (uint32_t)(lane >> 4) * 8 + (lane & 7);
    const uint32_t bK   = (uint32_t)((lane >> 3) & 1) * 16;

    float acc[4][4][4];
    #pragma unroll
    for (int mt = 0; mt < 4; mt++)
        #pragma unroll
        for (int nt = 0; nt < 4; nt++)
            #pragma unroll
            for (int i = 0; i < 4; i++) acc[mt][nt][i] = 0.f;

    const int r = tid >> 1, hf = tid & 1;

    for (int c = 0; c < 4; c++) {
        // ---- stage chunk c into smem (4 planes) ----
        {
            const size_t aoff = (size_t)(m0 + r) * C_ + c * 64 + hf * 32;
            const size_t boff = (size_t)(n0 + r) * C_ + c * 64 + hf * 32;
            const uint4* pah = (const uint4*)(Ahi + aoff);
            const uint4* pal = (const uint4*)(Alo + aoff);
            const uint4* pbh = (const uint4*)(Bhi + boff);
            const uint4* pbl = (const uint4*)(Blo + boff);
            #pragma unroll
            for (int j = 0; j < 4; j++) {
                uint32_t off = (uint32_t)r * 128 +
                               (((uint32_t)(hf * 64 + j * 16)) ^ ((uint32_t)(r & 7) << 4));
                uint4 v = pah[j]; STS128(sb + SM_AHI_ + off, v.x, v.y, v.z, v.w);
                v = pal[j];       STS128(sb + SM_ALO_ + off, v.x, v.y, v.z, v.w);
                v = pbh[j];       STS128(sb + SM_BHI_ + off, v.x, v.y, v.z, v.w);
                v = pbl[j];       STS128(sb + SM_BLO_ + off, v.x, v.y, v.z, v.w);
            }
        }
        __syncthreads();

        // ---- compute chunk ----
        #pragma unroll
        for (int kt = 0; kt < 4; kt++) {
            const uint32_t kx = ((aK + (uint32_t)kt * 32) ^ xm);
            const uint32_t kbx = ((bK + (uint32_t)kt * 32) ^ xm);
            uint32_t a[4][4], bh[4][2], bl[4][2];
            #pragma unroll
            for (int mt = 0; mt < 4; mt++) {
                uint32_t ad = sb + SM_AHI_ + (aRow + mt * 16) * 128 + kx;
                LDSM4(a[mt], ad);
            }
            #pragma unroll
            for (int p = 0; p < 2; p++) {
                uint32_t off = (bRow + p * 16) * 128 + kbx;
                uint32_t t[4];
                LDSM4(t, sb + SM_BHI_ + off);
                bh[2*p][0] = t[0]; bh[2*p][1] = t[1];
                bh[2*p+1][0] = t[2]; bh[2*p+1][1] = t[3];
                LDSM4(t, sb + SM_BLO_ + off);
                bl[2*p][0] = t[0]; bl[2*p][1] = t[1];
                bl[2*p+1][0] = t[2]; bl[2*p+1][1] = t[3];
            }
            #pragma unroll
            for (int mt = 0; mt < 4; mt++)
                #pragma unroll
                for (int nt = 0; nt < 4; nt++) {
                    MMA(acc[mt][nt], a[mt], bh[nt]);
                    MMA(acc[mt][nt], a[mt], bl[nt]);
                }
            // reload A-lo into same regs, third pass
            #pragma unroll
            for (int mt = 0; mt < 4; mt++) {
                uint32_t ad = sb + SM_ALO_ + (aRow + mt * 16) * 128 + kx;
                LDSM4(a[mt], ad);
            }
            #pragma unroll
            for (int mt = 0; mt < 4; mt++)
                #pragma unroll
                for (int nt = 0; nt < 4; nt++)
                    MMA(acc[mt][nt], a[mt], bh[nt]);
        }
        __syncthreads();
    }

    // ---- epilogue ----
    const int rowb = m0 + wm * 64 + (lane >> 2);
    const int colb = n0 + wn * 32 + (lane & 3) * 2;
    #pragma unroll
    for (int nt = 0; nt < 4; nt++) {
        const int col = colb + nt * 8;
        float2 bv = make_float2(0.f, 0.f);
        if (bias) bv = *(const float2*)(bias + col);
        #pragma unroll
        for (int mt = 0; mt < 4; mt++) {
            float2 v0 = make_float2(acc[mt][nt][0] + bv.x, acc[mt][nt][1] + bv.y);
            float2 v1 = make_float2(acc[mt][nt][2] + bv.x, acc[mt][nt][3] + bv.y);
            *(float2*)(C + (size_t)(rowb + mt * 16) * C_ + col)     = v0;
            *(float2*)(C + (size_t)(rowb + mt * 16 + 8) * C_ + col) = v1;
        }
    }
}

// ---------------- aux kernels (verified in R4) ----------------
__global__ void focus_kernel(const float* __restrict__ pos_enc,
                             const float* __restrict__ scale_param)
{
    const int lane = threadIdx.x & 31;
    const int warp = threadIdx.x >> 5;
    const int row  = blockIdx.x * 8 + warp;
    const int n    = row & (N_ - 1);
    float* qrow = g_Q + row * C_;
    float* krow = g_K + row * C_;
    const float* prow = pos_enc + n * C_;

    float tq3[8], tk3[8];
    float sq2 = 0.f, sq6 = 0.f, sk2 = 0.f, sk6 = 0.f;
    #pragma unroll
    for (int j = 0; j < 8; j++) {
        int c = lane + j * 32;
        float sp = scale_param[c];
        float s  = (sp > 20.f) ? sp : log1pf(expf(sp));
        float q  = fmaxf(qrow[c], 0.f);
        q = (q + 1e-6f) / s;
        float q3 = q * q * q;
        sq2 += q * q; sq6 += q3 * q3; tq3[j] = q3;
        float k = fmaxf(krow[c] + prow[c], 0.f);
        k = (k + 1e-6f) / s;
        float k3 = k * k * k;
        sk2 += k * k; sk6 += k3 * k3; tk3[j] = k3;
    }
    #pragma unroll
    for (int off = 16; off > 0; off >>= 1) {
        sq2 += __shfl_xor_sync(0xffffffffu, sq2, off);
        sq6 += __shfl_xor_sync(0xffffffffu, sq6, off);
        sk2 += __shfl_xor_sync(0xffffffffu, sk2, off);
        sk6 += __shfl_xor_sync(0xffffffffu, sk6, off);
    }
    float qf = sqrtf(sq2 / sq6);
    float kf = sqrtf(sk2 / sk6);
    #pragma unroll
    for (int j = 0; j < 8; j++) {
        int c = lane + j * 32;
        qrow[c] = tq3[j] * qf;
        krow[c] = tk3[j] * kf;
    }
}

__global__ void zero_kernel(float* __restrict__ p, int nElem)
{
    int i = blockIdx.x * 256 + threadIdx.x;
    if (i < nElem) p[i] = 0.f;
}

__global__ void kmean_kernel()
{
    const int c = threadIdx.x;
    const int b = blockIdx.y;
    const int chunk = blockIdx.x;
    const float* p = g_K + (b * N_ + chunk * 128) * C_ + c;
    float s = 0.f;
    #pragma unroll 8
    for (int i = 0; i < 128; i++) s += p[i * C_];
    atomicAdd(&g_kmean[b * C_ + c], s * (1.f / (float)N_));
}

__global__ void kvmat_kernel()
{
    const int bh = blockIdx.y;
    const int b  = bh >> 3, h = bh & 7;
    const int ns = blockIdx.x;
    const int t  = threadIdx.x;
    const int d  = t & 31, eg = t >> 5;
    __shared__ float ks[16][32], vs[16][32];
    float a0 = 0.f, a1 = 0.f, a2 = 0.f, a3 = 0.f;
    const int base = (b * N_ + ns * 512) * C_ + h * HD;

    for (int cc = 0; cc < 32; cc++) {
        const int off = base + cc * 16 * C_;
        {
            int nn = t >> 5, c = t & 31;
            ks[nn][c] = g_K[off + nn * C_ + c];
            vs[nn][c] = g_V[off + nn * C_ + c];
            int i2 = t + 256; nn = i2 >> 5; c = i2 & 31;
            ks[nn][c] = g_K[off + nn * C_ + c];
            vs[nn][c] = g_V[off + nn * C_ + c];
        }
        __syncthreads();
        #pragma unroll
        for (int nn = 0; nn < 16; nn++) {
            float  kd = ks[nn][d];
            float4 v4 = *(const float4*)&vs[nn][eg * 4];
            a0 += kd * v4.x; a1 += kd * v4.y; a2 += kd * v4.z; a3 += kd * v4.w;
        }
        __syncthreads();
    }
    const float sc = 1.f / (float)N_;
    const int  o  = (bh * HD + d) * HD + eg * 4;
    atomicAdd(&g_kvmat[o + 0], a0 * sc);
    atomicAdd(&g_kvmat[o + 1], a1 * sc);
    atomicAdd(&g_kvmat[o + 2], a2 * sc);
    atomicAdd(&g_kvmat[o + 3], a3 * sc);
}

__global__ __launch_bounds__(256, 1)
void attn_kernel()
{
    extern __shared__ float sm[];
    float* q_s = sm;
    float* kvs = q_s + 256 * 33;
    float* km  = kvs + NH * HD * HD;
    float* o_s = km + 256;

    const int b    = blockIdx.y;
    const int tile = blockIdx.x;
    const int row0 = b * N_ + tile * 32;
    const int t    = threadIdx.x;

    #pragma unroll
    for (int j = 0; j < 32; j++)
        q_s[t * 33 + j] = g_Q[(row0 + j) * C_ + t];
    for (int j = t; j < NH * HD * HD; j += 256)
        kvs[j] = g_kvmat[b * NH * HD * HD + j];
    km[t] = g_kmean[b * C_ + t];
    __syncthreads();

    const int n = t & 31, h = t >> 5;
    float qv[32];
    float z = 0.f;
    #pragma unroll
    for (int d = 0; d < 32; d++) {
        qv[d] = q_s[(h * HD + d) * 33 + n];
        z += qv[d] * km[h * HD + d];
    }
    float acc[32];
    #pragma unroll
    for (int e = 0; e < 32; e++) acc[e] = 0.f;
    const float* kvh = kvs + h * HD * HD;
    #pragma unroll 4
    for (int d = 0; d < 32; d++) {
        float qd = qv[d];
        #pragma unroll
        for (int e4 = 0; e4 < 8; e4++) {
            float4 kv = *(const float4*)&kvh[d * HD + e4 * 4];
            acc[e4*4+0] += qd * kv.x;
            acc[e4*4+1] += qd * kv.y;
            acc[e4*4+2] += qd * kv.z;
            acc[e4*4+3] += qd * kv.w;
        }
    }
    float zi = 1.f / (z + 1e-6f);
    #pragma unroll
    for (int e = 0; e < 32; e++)
        o_s[n * 257 + h * HD + e] = acc[e] * zi;
    __syncthreads();
    #pragma unroll
    for (int j = 0; j < 32; j++)
        g_O[(row0 + j) * C_ + t] = o_s[j * 257 + t];
}

__global__ void dwconv_kernel(const float* __restrict__ Wc,
                              const float* __restrict__ bc)
{
    const int c  = threadIdx.x;
    const int y  = blockIdx.x;
    const int b  = blockIdx.y;
    const int ch = c & (HD - 1);
    float w[25];
    #pragma unroll
    for (int i = 0; i < 25; i++) w[i] = Wc[ch * 25 + i];
    const float bias = bc[ch];

    const float* vb = g_V + (b * N_) * C_ + c;
    float*       ob = g_O + (b * N_) * C_ + c;

    float win[5][5];
    #pragma unroll
    for (int wy = 0; wy < 5; wy++) {
        int Y = y + wy - 2;
        bool yin = (Y >= 0) && (Y < 64);
        #pragma unroll
        for (int wx = 0; wx < 5; wx++) {
            int X = wx - 2;
            win[wy][wx] = (yin && X >= 0) ? vb[(Y * 64 + X) * C_] : 0.f;
        }
    }
    for (int x = 0; x < 64; x++) {
        float acc = bias;
        #pragma unroll
        for (int wy = 0; wy < 5; wy++)
            #pragma unroll
            for (int wx = 0; wx < 5; wx++)
                acc += win[wy][wx] * w[wy * 5 + wx];
        ob[(y * 64 + x) * C_] += acc;
        #pragma unroll
        for (int wy = 0; wy < 5; wy++)
            #pragma unroll
            for (int wx = 0; wx < 4; wx++) win[wy][wx] = win[wy][wx + 1];
        int X = x + 3;
        bool xin = X < 64;
        #pragma unroll
        for (int wy = 0; wy < 5; wy++) {
            int Y = y + wy - 2;
            win[wy][4] = (xin && Y >= 0 && Y < 64) ? vb[(Y * 64 + X) * C_] : 0.f;
        }
    }
}

// ------------------------------- host launcher -------------------------------
extern "C" void kernel_launch(void* const* d_in, const int* in_sizes, int n_in,
                              void* d_out, int out_size)
{
    const float* x     = (const float*)d_in[0];
    const float* Wq    = (const float*)d_in[1];
    const float* Wkv   = (const float*)d_in[2];
    const float* Wp    = (const float*)d_in[3];
    const float* bp    = (const float*)d_in[4];
    const float* scale = (const float*)d_in[5];
    const float* pos   = (const float*)d_in[6];
    const float* dwcw  = (const float*)d_in[7];
    const float* dwcb  = (const float*)d_in[8];
    float* out = (float*)d_out;

    float *Qp, *Kp, *Vp, *Op, *kmp, *kvp;
    __nv_bfloat16 *xhi, *xlo, *ohi, *olo, *whi, *wlo;
    cudaGetSymbolAddress((void**)&Qp,  g_Q);
    cudaGetSymbolAddress((void**)&Kp,  g_K);
    cudaGetSymbolAddress((void**)&Vp,  g_V);
    cudaGetSymbolAddress((void**)&Op,  g_O);
    cudaGetSymbolAddress((void**)&kmp, g_kmean);
    cudaGetSymbolAddress((void**)&kvp, g_kvmat);
    cudaGetSymbolAddress((void**)&xhi, g_xhi);
    cudaGetSymbolAddress((void**)&xlo, g_xlo);
    cudaGetSymbolAddress((void**)&ohi, g_ohi);
    cudaGetSymbolAddress((void**)&olo, g_olo);
    cudaGetSymbolAddress((void**)&whi, g_whi);
    cudaGetSymbolAddress((void**)&wlo, g_wlo);

    const int ATTN_SMEM = (256 * 33 + NH * HD * HD + 256 + 32 * 257) * 4;
    static bool attr_done = false;
    if (!attr_done) {
        cudaFuncSetAttribute(attn_kernel,
                             cudaFuncAttributeMaxDynamicSharedMemorySize, ATTN_SMEM);
        cudaFuncSetAttribute(gemm_hmma,
                             cudaFuncAttributeMaxDynamicSharedMemorySize, SM_GTOT);
        attr_done = true;
    }

    zero_kernel<<<(B_ * C_ + 255) / 256, 256>>>(kmp, B_ * C_);
    zero_kernel<<<(B_ * NH * HD * HD + 255) / 256, 256>>>(kvp, B_ * NH * HD * HD);

    cvt_hilo_kernel<<<(M_ * C_ / 4 + 255) / 256, 256>>>(x, xhi, xlo, M_ * C_ / 4);
    prep_w_kernel<<<dim3(C_, 4), 256>>>(Wq, Wkv, Wp);

    const int WS = C_ * C_;
    dim3 gg(2, M_ / 128);   // n fastest: the 2 CTAs sharing an A tile are adjacent
    gemm_hmma<<<gg, 256, SM_GTOT>>>(xhi, xlo, whi + 0 * WS, wlo + 0 * WS, nullptr, Qp);
    gemm_hmma<<<gg, 256, SM_GTOT>>>(xhi, xlo, whi + 1 * WS, wlo + 1 * WS, nullptr, Kp);
    gemm_hmma<<<gg, 256, SM_GTOT>>>(xhi, xlo, whi + 2 * WS, wlo + 2 * WS, nullptr, Vp);

    focus_kernel<<<M_ / 8, 256>>>(pos, scale);

    kmean_kernel<<<dim3(32, B_), 256>>>();
    kvmat_kernel<<<dim3(8, B_ * NH), 256>>>();

    attn_kernel<<<dim3(N_ / 32, B_), 256, ATTN_SMEM>>>();

    dwconv_kernel<<<dim3(64, B_), 256>>>(dwcw, dwcb);

    cvt_hilo_kernel<<<(M_ * C_ / 4 + 255) / 256, 256>>>(Op, ohi, olo, M_ * C_ / 4);
    gemm_hmma<<<gg, 256, SM_GTOT>>>(ohi, olo, whi + 3 * WS, wlo + 3 * WS, bp, out);
}

// round 7
// speedup vs baseline: 1.2650x; 1.0279x over previous
#include <cuda_runtime.h>
#include <cuda_bf16.h>
#include <cstdint>

#define B_   16
#define N_   4096
#define C_   256
#define NH   8
#define HD   32
#define M_   (B_ * N_)

// ---------------- scratch ----------------
__device__ __align__(16) float g_Q[M_ * C_];
__device__ __align__(16) float g_K[M_ * C_];
__device__ __align__(16) float g_V[M_ * C_];
__device__ __align__(16) float g_O[M_ * C_];
__device__ __align__(16) float g_kmean[B_ * C_];
__device__ __align__(16) float g_kvmat[B_ * NH * HD * HD];
__device__ __align__(16) __nv_bfloat16 g_xhi[M_ * C_];
__device__ __align__(16) __nv_bfloat16 g_xlo[M_ * C_];
__device__ __align__(16) __nv_bfloat16 g_ohi[M_ * C_];
__device__ __align__(16) __nv_bfloat16 g_olo[M_ * C_];
__device__ __align__(16) __nv_bfloat16 g_whi[4 * C_ * C_];   // [w][n][k]
__device__ __align__(16) __nv_bfloat16 g_wlo[4 * C_ * C_];

// ---------------- helpers ----------------
__device__ __forceinline__ uint32_t smem_u32(const void* p) {
    uint32_t a;
    asm("{ .reg .u64 t; cvta.to.shared.u64 t, %1; cvt.u32.u64 %0, t; }"
        : "=r"(a) : "l"(p));
    return a;
}
#define CPA(dst, src) \
    asm volatile("cp.async.cg.shared.global [%0], [%1], 16;" \
                 :: "r"(dst), "l"(__cvta_generic_to_global(src)) : "memory")
#define CPCOMMIT() asm volatile("cp.async.commit_group;" ::: "memory")
#define CPWAIT(n)  asm volatile("cp.async.wait_group %0;" :: "n"(n) : "memory")

#define LDSM4(d, addr) \
    asm volatile("ldmatrix.sync.aligned.m8n8.x4.shared.b16 {%0,%1,%2,%3}, [%4];" \
        : "=r"((d)[0]), "=r"((d)[1]), "=r"((d)[2]), "=r"((d)[3]) : "r"(addr))

#define MMA(c, a, b) \
    asm volatile("mma.sync.aligned.m16n8k16.row.col.f32.bf16.bf16.f32 " \
        "{%0,%1,%2,%3}, {%4,%5,%6,%7}, {%8,%9}, {%0,%1,%2,%3};" \
        : "+f"((c)[0]), "+f"((c)[1]), "+f"((c)[2]), "+f"((c)[3]) \
        : "r"((a)[0]), "r"((a)[1]), "r"((a)[2]), "r"((a)[3]), \
          "r"((b)[0]), "r"((b)[1]))

// ---------------- hi/lo conversion ----------------
union BF2U { __nv_bfloat162 b; uint32_t u; };
__device__ __forceinline__ void cvt4(float4 v, uint2& hi, uint2& lo) {
    __nv_bfloat16 h0 = __float2bfloat16_rn(v.x), h1 = __float2bfloat16_rn(v.y);
    __nv_bfloat16 h2 = __float2bfloat16_rn(v.z), h3 = __float2bfloat16_rn(v.w);
    __nv_bfloat16 l0 = __float2bfloat16_rn(v.x - __bfloat162float(h0));
    __nv_bfloat16 l1 = __float2bfloat16_rn(v.y - __bfloat162float(h1));
    __nv_bfloat16 l2 = __float2bfloat16_rn(v.z - __bfloat162float(h2));
    __nv_bfloat16 l3 = __float2bfloat16_rn(v.w - __bfloat162float(h3));
    BF2U a, b;
    a.b = __halves2bfloat162(h0, h1); b.b = __halves2bfloat162(h2, h3);
    hi = make_uint2(a.u, b.u);
    a.b = __halves2bfloat162(l0, l1); b.b = __halves2bfloat162(l2, l3);
    lo = make_uint2(a.u, b.u);
}

__global__ void cvt_hilo_kernel(const float* __restrict__ src,
                                __nv_bfloat16* __restrict__ hi,
                                __nv_bfloat16* __restrict__ lo, int n4)
{
    int i = blockIdx.x * 256 + threadIdx.x;
    if (i >= n4) return;
    float4 v = ((const float4*)src)[i];
    uint2 h, l;
    cvt4(v, h, l);
    ((uint2*)hi)[i] = h;
    ((uint2*)lo)[i] = l;
}

__global__ void prep_w_kernel(const float* __restrict__ Wq,
                              const float* __restrict__ Wkv,
                              const float* __restrict__ Wp)
{
    int k = blockIdx.x, w = blockIdx.y, n = threadIdx.x;
    float v;
    if      (w == 0) v = Wq[k * C_ + n];
    else if (w == 1) v = Wkv[k * 2 * C_ + n];
    else if (w == 2) v = Wkv[k * 2 * C_ + C_ + n];
    else             v = Wp[k * C_ + n];
    __nv_bfloat16 h = __float2bfloat16_rn(v);
    __nv_bfloat16 l = __float2bfloat16_rn(v - __bfloat162float(h));
    g_whi[(w * C_ + n) * C_ + k] = h;
    g_wlo[(w * C_ + n) * C_ + k] = l;
}

// ---------------- HMMA split-precision GEMM, cp.async double-buffered ---------
// C[M x 256] = (Ahi+Alo) @ (Bhi+Blo)^T (+bias).  B planes are [n][k] bf16.
// CTA 128x128, 256 thr, warp tile 64x32, K-chunks of 64, SW128-swizzled smem.
// Per stage: AHI 16K | ALO 16K | BHI 16K | BLO 16K = 64KB; two stages = 128KB.
#define STAGE_SZ 65536
#define PL_AHI 0
#define PL_ALO 16384
#define PL_BHI 32768
#define PL_BLO 49152
#define SM_GTOT (2 * STAGE_SZ)

__global__ void __launch_bounds__(256, 1)
gemm_hmma(const __nv_bfloat16* __restrict__ Ahi, const __nv_bfloat16* __restrict__ Alo,
          const __nv_bfloat16* __restrict__ Bhi, const __nv_bfloat16* __restrict__ Blo,
          const float* __restrict__ bias, float* __restrict__ C)
{
    extern __shared__ char smem[];
    const uint32_t sb = smem_u32(smem);
    const int tid  = threadIdx.x;
    const int lane = tid & 31, wid = tid >> 5;
    const int wm   = wid & 1,  wn  = wid >> 1;
    const int m0   = blockIdx.y * 128;
    const int n0   = blockIdx.x * 128;

    const uint32_t xm   = (uint32_t)(lane & 7) << 4;
    const uint32_t aRow = wm * 64 + (lane & 15);
    const uint32_t aK   = (uint32_t)(lane >> 4) * 16;
    const uint32_t bRow = wn * 32 + (uint32_t)(lane >> 4) * 8 + (lane & 7);
    const uint32_t bK   = (uint32_t)((lane >> 3) & 1) * 16;

    float acc[4][4][4];
    #pragma unroll
    for (int mt = 0; mt < 4; mt++)
        #pragma unroll
        for (int nt = 0; nt < 4; nt++)
            #pragma unroll
            for (int i = 0; i < 4; i++) acc[mt][nt][i] = 0.f;

    const int r = tid >> 1, hf = tid & 1;

    auto stage = [&](int c, uint32_t base) {
        const size_t aoff = (size_t)(m0 + r) * C_ + c * 64 + hf * 32;
        const size_t boff = (size_t)(n0 + r) * C_ + c * 64 + hf * 32;
        #pragma unroll
        for (int j = 0; j < 4; j++) {
            uint32_t off = (uint32_t)r * 128 +
                           (((uint32_t)(hf * 64 + j * 16)) ^ ((uint32_t)(r & 7) << 4));
            CPA(base + PL_AHI + off, Ahi + aoff + j * 8);
            CPA(base + PL_ALO + off, Alo + aoff + j * 8);
            CPA(base + PL_BHI + off, Bhi + boff + j * 8);
            CPA(base + PL_BLO + off, Blo + boff + j * 8);
        }
    };

    stage(0, sb);
    CPCOMMIT();

    for (int c = 0; c < 4; c++) {
        if (c + 1 < 4) {
            stage(c + 1, sb + (uint32_t)((c + 1) & 1) * STAGE_SZ);
            CPCOMMIT();
            CPWAIT(1);
        } else {
            CPWAIT(0);
        }
        __syncthreads();

        const uint32_t base = sb + (uint32_t)(c & 1) * STAGE_SZ;
        #pragma unroll
        for (int kt = 0; kt < 4; kt++) {
            const uint32_t kx  = ((aK + (uint32_t)kt * 32) ^ xm);
            const uint32_t kbx = ((bK + (uint32_t)kt * 32) ^ xm);
            uint32_t a[4][4], bh[4][2], bl[4][2];
            #pragma unroll
            for (int mt = 0; mt < 4; mt++)
                LDSM4(a[mt], base + PL_AHI + (aRow + mt * 16) * 128 + kx);
            #pragma unroll
            for (int p = 0; p < 2; p++) {
                uint32_t off = (bRow + p * 16) * 128 + kbx;
                uint32_t t[4];
                LDSM4(t, base + PL_BHI + off);
                bh[2*p][0] = t[0]; bh[2*p][1] = t[1];
                bh[2*p+1][0] = t[2]; bh[2*p+1][1] = t[3];
                LDSM4(t, base + PL_BLO + off);
                bl[2*p][0] = t[0]; bl[2*p][1] = t[1];
                bl[2*p+1][0] = t[2]; bl[2*p+1][1] = t[3];
            }
            #pragma unroll
            for (int mt = 0; mt < 4; mt++)
                #pragma unroll
                for (int nt = 0; nt < 4; nt++) {
                    MMA(acc[mt][nt], a[mt], bh[nt]);
                    MMA(acc[mt][nt], a[mt], bl[nt]);
                }
            #pragma unroll
            for (int mt = 0; mt < 4; mt++)
                LDSM4(a[mt], base + PL_ALO + (aRow + mt * 16) * 128 + kx);
            #pragma unroll
            for (int mt = 0; mt < 4; mt++)
                #pragma unroll
                for (int nt = 0; nt < 4; nt++)
                    MMA(acc[mt][nt], a[mt], bh[nt]);
        }
        __syncthreads();
    }

    // ---- epilogue ----
    const int rowb = m0 + wm * 64 + (lane >> 2);
    const int colb = n0 + wn * 32 + (lane & 3) * 2;
    #pragma unroll
    for (int nt = 0; nt < 4; nt++) {
        const int col = colb + nt * 8;
        float2 bv = make_float2(0.f, 0.f);
        if (bias) bv = *(const float2*)(bias + col);
        #pragma unroll
        for (int mt = 0; mt < 4; mt++) {
            float2 v0 = make_float2(acc[mt][nt][0] + bv.x, acc[mt][nt][1] + bv.y);
            float2 v1 = make_float2(acc[mt][nt][2] + bv.x, acc[mt][nt][3] + bv.y);
            *(float2*)(C + (size_t)(rowb + mt * 16) * C_ + col)     = v0;
            *(float2*)(C + (size_t)(rowb + mt * 16 + 8) * C_ + col) = v1;
        }
    }
}

// ---------------- focus nonlinearity + fused kmean accumulation ----------------
__global__ void focus_kernel(const float* __restrict__ pos_enc,
                             const float* __restrict__ scale_param)
{
    __shared__ float kpart[256];
    const int lane = threadIdx.x & 31;
    const int warp = threadIdx.x >> 5;
    const int row  = blockIdx.x * 8 + warp;
    const int n    = row & (N_ - 1);
    const int b    = row >> 12;            // N_ = 4096 rows per batch
    float* qrow = g_Q + row * C_;
    float* krow = g_K + row * C_;
    const float* prow = pos_enc + n * C_;

    kpart[threadIdx.x] = 0.f;
    __syncthreads();

    float tq3[8], tk3[8];
    float sq2 = 0.f, sq6 = 0.f, sk2 = 0.f, sk6 = 0.f;
    #pragma unroll
    for (int j = 0; j < 8; j++) {
        int c = lane + j * 32;
        float sp = scale_param[c];
        float s  = (sp > 20.f) ? sp : log1pf(expf(sp));
        float q  = fmaxf(qrow[c], 0.f);
        q = (q + 1e-6f) / s;
        float q3 = q * q * q;
        sq2 += q * q; sq6 += q3 * q3; tq3[j] = q3;
        float k = fmaxf(krow[c] + prow[c], 0.f);
        k = (k + 1e-6f) / s;
        float k3 = k * k * k;
        sk2 += k * k; sk6 += k3 * k3; tk3[j] = k3;
    }
    #pragma unroll
    for (int off = 16; off > 0; off >>= 1) {
        sq2 += __shfl_xor_sync(0xffffffffu, sq2, off);
        sq6 += __shfl_xor_sync(0xffffffffu, sq6, off);
        sk2 += __shfl_xor_sync(0xffffffffu, sk2, off);
        sk6 += __shfl_xor_sync(0xffffffffu, sk6, off);
    }
    float qf = sqrtf(sq2 / sq6);
    float kf = sqrtf(sk2 / sk6);
    #pragma unroll
    for (int j = 0; j < 8; j++) {
        int c = lane + j * 32;
        float kv = tk3[j] * kf;
        qrow[c] = tq3[j] * qf;
        krow[c] = kv;
        atomicAdd(&kpart[c], kv);          // per-block kmean partial
    }
    __syncthreads();
    if (warp == 0) {
        #pragma unroll
        for (int j = 0; j < 8; j++) {
            int c = lane + j * 32;
            atomicAdd(&g_kmean[b * C_ + c], kpart[c] * (1.f / (float)N_));
        }
    }
}

__global__ void zero_kernel(float* __restrict__ p, int nElem)
{
    int i = blockIdx.x * 256 + threadIdx.x;
    if (i < nElem) p[i] = 0.f;
}

// kvmat[b,h,d,e] = sum_n K[b,n,h,d]*V[b,n,h,e] / N
__global__ void kvmat_kernel()
{
    const int bh = blockIdx.y;
    const int b  = bh >> 3, h = bh & 7;
    const int ns = blockIdx.x;
    const int t  = threadIdx.x;
    const int d  = t & 31, eg = t >> 5;
    __shared__ float ks[16][32], vs[16][32];
    float a0 = 0.f, a1 = 0.f, a2 = 0.f, a3 = 0.f;
    const int base = (b * N_ + ns * 512) * C_ + h * HD;

    for (int cc = 0; cc < 32; cc++) {
        const int off = base + cc * 16 * C_;
        {
            int nn = t >> 5, c = t & 31;
            ks[nn][c] = g_K[off + nn * C_ + c];
            vs[nn][c] = g_V[off + nn * C_ + c];
            int i2 = t + 256; nn = i2 >> 5; c = i2 & 31;
            ks[nn][c] = g_K[off + nn * C_ + c];
            vs[nn][c] = g_V[off + nn * C_ + c];
        }
        __syncthreads();
        #pragma unroll
        for (int nn = 0; nn < 16; nn++) {
            float  kd = ks[nn][d];
            float4 v4 = *(const float4*)&vs[nn][eg * 4];
            a0 += kd * v4.x; a1 += kd * v4.y; a2 += kd * v4.z; a3 += kd * v4.w;
        }
        __syncthreads();
    }
    const float sc = 1.f / (float)N_;
    const int  o  = (bh * HD + d) * HD + eg * 4;
    atomicAdd(&g_kvmat[o + 0], a0 * sc);
    atomicAdd(&g_kvmat[o + 1], a1 * sc);
    atomicAdd(&g_kvmat[o + 2], a2 * sc);
    atomicAdd(&g_kvmat[o + 3], a3 * sc);
}

__global__ __launch_bounds__(256, 1)
void attn_kernel()
{
    extern __shared__ float sm[];
    float* q_s = sm;
    float* kvs = q_s + 256 * 33;
    float* km  = kvs + NH * HD * HD;
    float* o_s = km + 256;

    const int b    = blockIdx.y;
    const int tile = blockIdx.x;
    const int row0 = b * N_ + tile * 32;
    const int t    = threadIdx.x;

    #pragma unroll
    for (int j = 0; j < 32; j++)
        q_s[t * 33 + j] = g_Q[(row0 + j) * C_ + t];
    for (int j = t; j < NH * HD * HD; j += 256)
        kvs[j] = g_kvmat[b * NH * HD * HD + j];
    km[t] = g_kmean[b * C_ + t];
    __syncthreads();

    const int n = t & 31, h = t >> 5;
    float qv[32];
    float z = 0.f;
    #pragma unroll
    for (int d = 0; d < 32; d++) {
        qv[d] = q_s[(h * HD + d) * 33 + n];
        z += qv[d] * km[h * HD + d];
    }
    float acc[32];
    #pragma unroll
    for (int e = 0; e < 32; e++) acc[e] = 0.f;
    const float* kvh = kvs + h * HD * HD;
    #pragma unroll 4
    for (int d = 0; d < 32; d++) {
        float qd = qv[d];
        #pragma unroll
        for (int e4 = 0; e4 < 8; e4++) {
            float4 kv = *(const float4*)&kvh[d * HD + e4 * 4];
            acc[e4*4+0] += qd * kv.x;
            acc[e4*4+1] += qd * kv.y;
            acc[e4*4+2] += qd * kv.z;
            acc[e4*4+3] += qd * kv.w;
        }
    }
    float zi = 1.f / (z + 1e-6f);
    #pragma unroll
    for (int e = 0; e < 32; e++)
        o_s[n * 257 + h * HD + e] = acc[e] * zi;
    __syncthreads();
    #pragma unroll
    for (int j = 0; j < 32; j++)
        g_O[(row0 + j) * C_ + t] = o_s[j * 257 + t];
}

// depthwise 5x5 conv over V + O(attn), emits hi/lo bf16 planes directly
__global__ void dwconv_kernel(const float* __restrict__ Wc,
                              const float* __restrict__ bc)
{
    const int c  = threadIdx.x;
    const int y  = blockIdx.x;
    const int b  = blockIdx.y;
    const int ch = c & (HD - 1);
    float w[25];
    #pragma unroll
    for (int i = 0; i < 25; i++) w[i] = Wc[ch * 25 + i];
    const float bias = bc[ch];

    const float* vb = g_V + (b * N_) * C_ + c;
    const float* ob = g_O + (b * N_) * C_ + c;
    __nv_bfloat16* ph = g_ohi + (size_t)(b * N_) * C_ + c;
    __nv_bfloat16* pl = g_olo + (size_t)(b * N_) * C_ + c;

    float win[5][5];
    #pragma unroll
    for (int wy = 0; wy < 5; wy++) {
        int Y = y + wy - 2;
        bool yin = (Y >= 0) && (Y < 64);
        #pragma unroll
        for (int wx = 0; wx < 5; wx++) {
            int X = wx - 2;
            win[wy][wx] = (yin && X >= 0) ? vb[(Y * 64 + X) * C_] : 0.f;
        }
    }
    for (int x = 0; x < 64; x++) {
        float acc = bias;
        #pragma unroll
        for (int wy = 0; wy < 5; wy++)
            #pragma unroll
            for (int wx = 0; wx < 5; wx++)
                acc += win[wy][wx] * w[wy * 5 + wx];
        float val = ob[(y * 64 + x) * C_] + acc;
        __nv_bfloat16 h = __float2bfloat16_rn(val);
        __nv_bfloat16 l = __float2bfloat16_rn(val - __bfloat162float(h));
        ph[(y * 64 + x) * C_] = h;
        pl[(y * 64 + x) * C_] = l;
        #pragma unroll
        for (int wy = 0; wy < 5; wy++)
            #pragma unroll
            for (int wx = 0; wx < 4; wx++) win[wy][wx] = win[wy][wx + 1];
        int X = x + 3;
        bool xin = X < 64;
        #pragma unroll
        for (int wy = 0; wy < 5; wy++) {
            int Y = y + wy - 2;
            win[wy][4] = (xin && Y >= 0 && Y < 64) ? vb[(Y * 64 + X) * C_] : 0.f;
        }
    }
}

// ------------------------------- host launcher -------------------------------
extern "C" void kernel_launch(void* const* d_in, const int* in_sizes, int n_in,
                              void* d_out, int out_size)
{
    const float* x     = (const float*)d_in[0];
    const float* Wq    = (const float*)d_in[1];
    const float* Wkv   = (const float*)d_in[2];
    const float* Wp    = (const float*)d_in[3];
    const float* bp    = (const float*)d_in[4];
    const float* scale = (const float*)d_in[5];
    const float* pos   = (const float*)d_in[6];
    const float* dwcw  = (const float*)d_in[7];
    const float* dwcb  = (const float*)d_in[8];
    float* out = (float*)d_out;

    float *Qp, *Kp, *Vp, *Op, *kmp, *kvp;
    __nv_bfloat16 *xhi, *xlo, *ohi, *olo, *whi, *wlo;
    cudaGetSymbolAddress((void**)&Qp,  g_Q);
    cudaGetSymbolAddress((void**)&Kp,  g_K);
    cudaGetSymbolAddress((void**)&Vp,  g_V);
    cudaGetSymbolAddress((void**)&Op,  g_O);
    cudaGetSymbolAddress((void**)&kmp, g_kmean);
    cudaGetSymbolAddress((void**)&kvp, g_kvmat);
    cudaGetSymbolAddress((void**)&xhi, g_xhi);
    cudaGetSymbolAddress((void**)&xlo, g_xlo);
    cudaGetSymbolAddress((void**)&ohi, g_ohi);
    cudaGetSymbolAddress((void**)&olo, g_olo);
    cudaGetSymbolAddress((void**)&whi, g_whi);
    cudaGetSymbolAddress((void**)&wlo, g_wlo);

    const int ATTN_SMEM = (256 * 33 + NH * HD * HD + 256 + 32 * 257) * 4;
    static bool attr_done = false;
    if (!attr_done) {
        cudaFuncSetAttribute(attn_kernel,
                             cudaFuncAttributeMaxDynamicSharedMemorySize, ATTN_SMEM);
        cudaFuncSetAttribute(gemm_hmma,
                             cudaFuncAttributeMaxDynamicSharedMemorySize, SM_GTOT);
        attr_done = true;
    }

    zero_kernel<<<(B_ * C_ + 255) / 256, 256>>>(kmp, B_ * C_);
    zero_kernel<<<(B_ * NH * HD * HD + 255) / 256, 256>>>(kvp, B_ * NH * HD * HD);

    cvt_hilo_kernel<<<(M_ * C_ / 4 + 255) / 256, 256>>>(x, xhi, xlo, M_ * C_ / 4);
    prep_w_kernel<<<dim3(C_, 4), 256>>>(Wq, Wkv, Wp);

    const int WS = C_ * C_;
    dim3 gg(2, M_ / 128);
    gemm_hmma<<<gg, 256, SM_GTOT>>>(xhi, xlo, whi + 0 * WS, wlo + 0 * WS, nullptr, Qp);
    gemm_hmma<<<gg, 256, SM_GTOT>>>(xhi, xlo, whi + 1 * WS, wlo + 1 * WS, nullptr, Kp);
    gemm_hmma<<<gg, 256, SM_GTOT>>>(xhi, xlo, whi + 2 * WS, wlo + 2 * WS, nullptr, Vp);

    focus_kernel<<<M_ / 8, 256>>>(pos, scale);      // also accumulates kmean

    kvmat_kernel<<<dim3(8, B_ * NH), 256>>>();

    attn_kernel<<<dim3(N_ / 32, B_), 256, ATTN_SMEM>>>();

    dwconv_kernel<<<dim3(64, B_), 256>>>(dwcw, dwcb);  // emits ohi/olo

    gemm_hmma<<<gg, 256, SM_GTOT>>>(ohi, olo, whi + 3 * WS, wlo + 3 * WS, bp, out);
}